// round 1
// baseline (speedup 1.0000x reference)
#include <cuda_runtime.h>
#include <math.h>

#define BATCH 8192
#define CONV_OUT 5104      // 8 * 22 * 29
#define SSZ 32
#define NSZ 19
#define UNFOLDS 6
#define L2E 1.4426950408889634f

// ---------------- static scratch (no allocations allowed) ----------------
__device__ float g_act[(size_t)BATCH * CONV_OUT];   // conv+ELU output, 167 MB
__device__ float g_h[BATCH * 64];                   // FC1+relu output
__device__ float g_sens[BATCH * 64];                // [t][0..18]=wnum_s+g*vleak, [t][32..50]=wden_s
// transformed recurrent params, [src][32] stride-32 padded
__device__ float g_rP[NSZ * 32], g_rQ[NSZ * 32], g_rA[NSZ * 32], g_rW[NSZ * 32];
__device__ float g_cmt[32], g_cg[32], g_gvl[32];
// transformed sensory params, [s][n] stride NSZ
__device__ float g_sP[SSZ * NSZ], g_sQ[SSZ * NSZ], g_sA[SSZ * NSZ], g_sW[SSZ * NSZ];

__device__ __forceinline__ float fast_ex2(float x) {
    float y; asm("ex2.approx.f32 %0, %1;" : "=f"(y) : "f"(x)); return y;
}
__device__ __forceinline__ float fast_rcp(float x) {
    float y; asm("rcp.approx.f32 %0, %1;" : "=f"(y) : "f"(x)); return y;
}

// ---------------- K0: parameter transforms (runs once per launch) ----------------
__global__ void k_prep(const float* __restrict__ w,     const float* __restrict__ mu,
                       const float* __restrict__ sigma, const float* __restrict__ erev,
                       const float* __restrict__ mask,
                       const float* __restrict__ gleak, const float* __restrict__ vleak,
                       const float* __restrict__ cm,
                       const float* __restrict__ sw,    const float* __restrict__ smu,
                       const float* __restrict__ ssig,  const float* __restrict__ serev,
                       const float* __restrict__ smask) {
    int i = threadIdx.x;
    if (i < NSZ * NSZ) {
        int s = i / NSZ, n = i % NSZ;
        float wp = log1pf(expf(w[i])) * mask[i];     // softplus(w) * mask
        g_rP[s * 32 + n] = -sigma[i] * L2E;          // exp(-sigma*(v-mu)) = ex2(P*v + Q)
        g_rQ[s * 32 + n] =  sigma[i] * mu[i] * L2E;
        g_rA[s * 32 + n] =  wp * erev[i];
        g_rW[s * 32 + n] =  wp;
    }
    if (i < SSZ * NSZ) {
        float sp = log1pf(expf(sw[i])) * smask[i];
        g_sP[i] = -ssig[i] * L2E;
        g_sQ[i] =  ssig[i] * smu[i] * L2E;
        g_sA[i] =  sp * serev[i];
        g_sW[i] =  sp;
    }
    if (i < NSZ) {
        float g   = log1pf(expf(gleak[i]));
        float cmt = log1pf(expf(cm[i])) * (float)UNFOLDS;
        g_cmt[i] = cmt;
        g_cg[i]  = cmt + g + 1e-8f;                  // denom constant part (+EPS)
        g_gvl[i] = g * vleak[i];                     // numerator constant part
    }
}

// ---------------- K1: conv 2x2 VALID + ELU, flattened NCHW ----------------
__global__ void k_conv(const float* __restrict__ x, const float* __restrict__ cw,
                       const float* __restrict__ cb) {
    __shared__ float sx[3 * 23 * 30];   // 2070
    __shared__ float swt[96];
    __shared__ float sb[8];
    int b = blockIdx.x;
    const float* xb = x + (size_t)b * 2070;
    for (int i = threadIdx.x; i < 2070; i += blockDim.x) sx[i] = xb[i];
    if (threadIdx.x < 96) swt[threadIdx.x] = cw[threadIdx.x];
    if (threadIdx.x < 8)  sb[threadIdx.x] = cb[threadIdx.x];
    __syncthreads();
    float* ob = g_act + (size_t)b * CONV_OUT;
    for (int o = threadIdx.x; o < CONV_OUT; o += blockDim.x) {
        int c = o / 638;          // 22*29
        int r = o % 638;
        int i = r / 29, j = r % 29;
        float acc = sb[c];
        #pragma unroll
        for (int ci = 0; ci < 3; ci++)
            #pragma unroll
            for (int ki = 0; ki < 2; ki++)
                #pragma unroll
                for (int kj = 0; kj < 2; kj++)
                    acc = fmaf(sx[ci * 690 + (i + ki) * 30 + (j + kj)],
                               swt[c * 12 + ci * 4 + ki * 2 + kj], acc);
        ob[o] = acc > 0.f ? acc : expm1f(acc);       // ELU
    }
}

// ---------------- K2: FC1 GEMM (8192x64, K=5104) + bias + relu ----------------
__global__ void k_fc1(const float* __restrict__ fw, const float* __restrict__ fb) {
    __shared__ float As[16][68];
    __shared__ float Bs[16][68];
    int tid = threadIdx.x;
    int block_m = blockIdx.x * 64;
    int tx = tid & 15;         // output-col group
    int ty = tid >> 4;         // batch-row group
    int lm = tid >> 2;         // 0..63 load row
    int lk = (tid & 3) << 2;   // 0,4,8,12
    const float* aptr = g_act + (size_t)(block_m + lm) * CONV_OUT + lk;
    const float* bptr = fw + (size_t)lm * CONV_OUT + lk;
    float acc[4][4];
    #pragma unroll
    for (int i = 0; i < 4; i++)
        #pragma unroll
        for (int j = 0; j < 4; j++) acc[i][j] = 0.f;
    for (int k0 = 0; k0 < CONV_OUT; k0 += 16) {
        float4 a = *(const float4*)(aptr + k0);
        float4 b = *(const float4*)(bptr + k0);
        As[lk + 0][lm] = a.x; As[lk + 1][lm] = a.y; As[lk + 2][lm] = a.z; As[lk + 3][lm] = a.w;
        Bs[lk + 0][lm] = b.x; Bs[lk + 1][lm] = b.y; Bs[lk + 2][lm] = b.z; Bs[lk + 3][lm] = b.w;
        __syncthreads();
        #pragma unroll
        for (int k = 0; k < 16; k++) {
            float ar[4], br[4];
            #pragma unroll
            for (int i = 0; i < 4; i++) ar[i] = As[k][ty * 4 + i];
            #pragma unroll
            for (int j = 0; j < 4; j++) br[j] = Bs[k][tx * 4 + j];
            #pragma unroll
            for (int i = 0; i < 4; i++)
                #pragma unroll
                for (int j = 0; j < 4; j++) acc[i][j] = fmaf(ar[i], br[j], acc[i][j]);
        }
        __syncthreads();
    }
    #pragma unroll
    for (int i = 0; i < 4; i++) {
        int m = block_m + ty * 4 + i;
        #pragma unroll
        for (int j = 0; j < 4; j++) {
            int n = tx * 4 + j;
            float v = acc[i][j] + fb[n];
            g_h[m * 64 + n] = v > 0.f ? v : 0.f;     // relu
        }
    }
}

// ---------------- K3: FC2 + input-affine + sensory synapse sums ----------------
__global__ void k_sens(const float* __restrict__ fc2w, const float* __restrict__ fc2b,
                       const float* __restrict__ inw,  const float* __restrict__ inb) {
    __shared__ float sh[8][33];
    int warp = threadIdx.x >> 5, lane = threadIdx.x & 31;
    int t = blockIdx.x * 8 + warp;
    float h0 = g_h[t * 64 + lane];
    float h1 = g_h[t * 64 + 32 + lane];
    float y = fc2b[lane];                            // lane = output j (all 32)
    #pragma unroll
    for (int o = 0; o < 32; o++) {
        float hb = __shfl_sync(0xffffffffu, h0, o);
        y = fmaf(fc2w[lane * 64 + o], hb, y);
    }
    #pragma unroll
    for (int o = 0; o < 32; o++) {
        float hb = __shfl_sync(0xffffffffu, h1, o);
        y = fmaf(fc2w[lane * 64 + 32 + o], hb, y);
    }
    float seq = fmaf(y, inw[lane], inb[lane]);
    sh[warp][lane] = seq;
    __syncwarp();
    if (lane < NSZ) {
        float wn = 0.f, wd = 0.f;
        #pragma unroll
        for (int s = 0; s < SSZ; s++) {
            float arg = fmaf(g_sP[s * NSZ + lane], sh[warp][s], g_sQ[s * NSZ + lane]);
            float r = fast_rcp(1.0f + fast_ex2(arg));   // sigmoid
            wn = fmaf(g_sA[s * NSZ + lane], r, wn);
            wd = fmaf(g_sW[s * NSZ + lane], r, wd);
        }
        g_sens[t * 64 + lane]      = wn + g_gvl[lane];  // fold g*vleak into numerator base
        g_sens[t * 64 + 32 + lane] = wd;
    }
}

// ---------------- K4: serial LTC scan (single warp; lane = target neuron) ----------------
__global__ void k_scan(float* __restrict__ out, const float* __restrict__ ow,
                       const float* __restrict__ ob) {
    int lane = threadIdx.x;
    bool act = lane < NSZ;
    float P[NSZ], Q[NSZ], A[NSZ], W[NSZ];
    #pragma unroll
    for (int s = 0; s < NSZ; s++) {
        P[s] = act ? g_rP[s * 32 + lane] : 0.f;
        Q[s] = act ? g_rQ[s * 32 + lane] : 0.f;
        A[s] = act ? g_rA[s * 32 + lane] : 0.f;
        W[s] = act ? g_rW[s * 32 + lane] : 0.f;
    }
    float cmt = act ? g_cmt[lane] : 0.f;
    float cg  = act ? g_cg[lane]  : 1.f;
    float ow0 = ow[0], ob0 = ob[0];
    float v = 0.f;
    float wnb = act ? g_sens[lane]      : 0.f;
    float wdb = act ? g_sens[32 + lane] : 0.f;
    for (int t = 0; t < BATCH; t++) {
        // prefetch next step's sensory sums (hidden behind ~1900 cyc of unfolds)
        float wn_nx = 0.f, wd_nx = 0.f;
        if (act && t + 1 < BATCH) {
            wn_nx = g_sens[(t + 1) * 64 + lane];
            wd_nx = g_sens[(t + 1) * 64 + 32 + lane];
        }
        for (int u = 0; u < UNFOLDS; u++) {
            float wn = wnb, wd = wdb;
            #pragma unroll
            for (int s = 0; s < NSZ; s++) {
                float vs  = __shfl_sync(0xffffffffu, v, s);
                float arg = fmaf(P[s], vs, Q[s]);
                float r   = fast_rcp(1.0f + fast_ex2(arg));   // sigmoid(sigma*(v_s - mu))
                wn = fmaf(A[s], r, wn);
                wd = fmaf(W[s], r, wd);
            }
            v = fmaf(cmt, v, wn) * fast_rcp(cg + wd);
        }
        if (lane == 0) out[t] = fmaf(v, ow0, ob0);
        wnb = wn_nx; wdb = wd_nx;
    }
}

// ---------------- launch ----------------
extern "C" void kernel_launch(void* const* d_in, const int* in_sizes, int n_in,
                              void* d_out, int out_size) {
    const float* x        = (const float*)d_in[0];
    const float* conv_w   = (const float*)d_in[1];
    const float* conv_b   = (const float*)d_in[2];
    const float* fc1_w    = (const float*)d_in[3];
    const float* fc1_b    = (const float*)d_in[4];
    const float* fc2_w    = (const float*)d_in[5];
    const float* fc2_b    = (const float*)d_in[6];
    const float* input_w  = (const float*)d_in[7];
    const float* input_b  = (const float*)d_in[8];
    const float* s_w      = (const float*)d_in[9];
    const float* s_mu     = (const float*)d_in[10];
    const float* s_sigma  = (const float*)d_in[11];
    const float* s_erev   = (const float*)d_in[12];
    const float* s_mask   = (const float*)d_in[13];
    const float* w        = (const float*)d_in[14];
    const float* mu       = (const float*)d_in[15];
    const float* sigma    = (const float*)d_in[16];
    const float* erev     = (const float*)d_in[17];
    const float* mask     = (const float*)d_in[18];
    const float* gleak    = (const float*)d_in[19];
    const float* vleak    = (const float*)d_in[20];
    const float* cm       = (const float*)d_in[21];
    const float* output_w = (const float*)d_in[22];
    const float* output_b = (const float*)d_in[23];

    k_prep<<<1, 640>>>(w, mu, sigma, erev, mask, gleak, vleak, cm,
                       s_w, s_mu, s_sigma, s_erev, s_mask);
    k_conv<<<BATCH, 256>>>(x, conv_w, conv_b);
    k_fc1<<<BATCH / 64, 256>>>(fc1_w, fc1_b);
    k_sens<<<BATCH / 8, 256>>>(fc2_w, fc2_b, input_w, input_b);
    k_scan<<<1, 32>>>((float*)d_out, output_w, output_b);
}

// round 2
// speedup vs baseline: 3.5974x; 3.5974x over previous
#include <cuda_runtime.h>
#include <math.h>

#define BATCH 8192
#define CONV_OUT 5104      // 8 * 22 * 29
#define SSZ 32
#define NSZ 19
#define UNFOLDS 6
#define L2E 1.4426950408889634f

// ---------------- static scratch (no allocations allowed) ----------------
__device__ float g_act[(size_t)BATCH * CONV_OUT];   // conv+ELU output, 167 MB
__device__ float g_h[BATCH * 64];                   // FC1+relu output
__device__ float g_sens[BATCH * 64];                // [t][0..18]=wnum_s+g*vleak, [t][32..50]=wden_s
// transformed recurrent params for tanh form, [src][32] stride-32 padded
__device__ float g_rP[NSZ * 32], g_rQ[NSZ * 32], g_rA[NSZ * 32], g_rW[NSZ * 32];
__device__ float g_cmt[32], g_cg2[32], g_gvl[32], g_hA[32];
// transformed sensory params (sigmoid ex2 form), [s][n] stride NSZ
__device__ float g_sP[SSZ * NSZ], g_sQ[SSZ * NSZ], g_sA[SSZ * NSZ], g_sW[SSZ * NSZ];

__device__ __forceinline__ float fast_ex2(float x) {
    float y; asm("ex2.approx.f32 %0, %1;" : "=f"(y) : "f"(x)); return y;
}
__device__ __forceinline__ float fast_rcp(float x) {
    float y; asm("rcp.approx.f32 %0, %1;" : "=f"(y) : "f"(x)); return y;
}
__device__ __forceinline__ float fast_tanh(float x) {
    float y; asm("tanh.approx.f32 %0, %1;" : "=f"(y) : "f"(x)); return y;
}

// ---------------- K0: parameter transforms (runs once per launch) ----------------
__global__ void k_prep(const float* __restrict__ w,     const float* __restrict__ mu,
                       const float* __restrict__ sigma, const float* __restrict__ erev,
                       const float* __restrict__ mask,
                       const float* __restrict__ gleak, const float* __restrict__ vleak,
                       const float* __restrict__ cm,
                       const float* __restrict__ sw,    const float* __restrict__ smu,
                       const float* __restrict__ ssig,  const float* __restrict__ serev,
                       const float* __restrict__ smask) {
    int i = threadIdx.x;
    if (i < NSZ * NSZ) {
        int s = i / NSZ, n = i % NSZ;
        float wp = log1pf(expf(w[i])) * mask[i];     // softplus(w) * mask
        // sigmoid(sigma*(v-mu)) = 0.5 + 0.5*tanh(0.5*sigma*(v-mu))
        g_rP[s * 32 + n] =  0.5f * sigma[i];
        g_rQ[s * 32 + n] = -0.5f * sigma[i] * mu[i];
        g_rA[s * 32 + n] =  0.5f * wp * erev[i];     // coefficient of tanh in numerator
        g_rW[s * 32 + n] =  0.5f * wp;               // coefficient of tanh in denominator
    }
    if (i < SSZ * NSZ) {
        float sp = log1pf(expf(sw[i])) * smask[i];
        g_sP[i] = -ssig[i] * L2E;
        g_sQ[i] =  ssig[i] * smu[i] * L2E;
        g_sA[i] =  sp * serev[i];
        g_sW[i] =  sp;
    }
    __syncthreads();
    if (i < NSZ) {
        float g   = log1pf(expf(gleak[i]));
        float cmt = log1pf(expf(cm[i])) * (float)UNFOLDS;
        float sumA = 0.f, sumW = 0.f;
        for (int s = 0; s < NSZ; s++) { sumA += g_rA[s * 32 + i]; sumW += g_rW[s * 32 + i]; }
        g_cmt[i] = cmt;
        g_cg2[i] = cmt + g + 1e-8f + sumW;           // denom const (+EPS +0.5*sum wp)
        g_gvl[i] = g * vleak[i];                     // numerator constant part
        g_hA[i]  = sumA;                             // numerator constant: 0.5*sum(wp*erev)
    }
}

// ---------------- K1: conv 2x2 VALID + ELU, flattened NCHW ----------------
__global__ void k_conv(const float* __restrict__ x, const float* __restrict__ cw,
                       const float* __restrict__ cb) {
    __shared__ float sx[3 * 23 * 30];   // 2070
    __shared__ float swt[96];
    __shared__ float sb[8];
    int b = blockIdx.x;
    const float* xb = x + (size_t)b * 2070;
    for (int i = threadIdx.x; i < 2070; i += blockDim.x) sx[i] = xb[i];
    if (threadIdx.x < 96) swt[threadIdx.x] = cw[threadIdx.x];
    if (threadIdx.x < 8)  sb[threadIdx.x] = cb[threadIdx.x];
    __syncthreads();
    float* ob = g_act + (size_t)b * CONV_OUT;
    for (int o = threadIdx.x; o < CONV_OUT; o += blockDim.x) {
        int c = o / 638;          // 22*29
        int r = o % 638;
        int i = r / 29, j = r % 29;
        float acc = sb[c];
        #pragma unroll
        for (int ci = 0; ci < 3; ci++)
            #pragma unroll
            for (int ki = 0; ki < 2; ki++)
                #pragma unroll
                for (int kj = 0; kj < 2; kj++)
                    acc = fmaf(sx[ci * 690 + (i + ki) * 30 + (j + kj)],
                               swt[c * 12 + ci * 4 + ki * 2 + kj], acc);
        ob[o] = acc > 0.f ? acc : expm1f(acc);       // ELU
    }
}

// ---------------- K2: FC1 GEMM (8192x64, K=5104) + bias + relu ----------------
__global__ void k_fc1(const float* __restrict__ fw, const float* __restrict__ fb) {
    __shared__ float As[16][68];
    __shared__ float Bs[16][68];
    int tid = threadIdx.x;
    int block_m = blockIdx.x * 64;
    int tx = tid & 15;         // output-col group
    int ty = tid >> 4;         // batch-row group
    int lm = tid >> 2;         // 0..63 load row
    int lk = (tid & 3) << 2;   // 0,4,8,12
    const float* aptr = g_act + (size_t)(block_m + lm) * CONV_OUT + lk;
    const float* bptr = fw + (size_t)lm * CONV_OUT + lk;
    float acc[4][4];
    #pragma unroll
    for (int i = 0; i < 4; i++)
        #pragma unroll
        for (int j = 0; j < 4; j++) acc[i][j] = 0.f;
    for (int k0 = 0; k0 < CONV_OUT; k0 += 16) {
        float4 a = *(const float4*)(aptr + k0);
        float4 b = *(const float4*)(bptr + k0);
        As[lk + 0][lm] = a.x; As[lk + 1][lm] = a.y; As[lk + 2][lm] = a.z; As[lk + 3][lm] = a.w;
        Bs[lk + 0][lm] = b.x; Bs[lk + 1][lm] = b.y; Bs[lk + 2][lm] = b.z; Bs[lk + 3][lm] = b.w;
        __syncthreads();
        #pragma unroll
        for (int k = 0; k < 16; k++) {
            float ar[4], br[4];
            #pragma unroll
            for (int i = 0; i < 4; i++) ar[i] = As[k][ty * 4 + i];
            #pragma unroll
            for (int j = 0; j < 4; j++) br[j] = Bs[k][tx * 4 + j];
            #pragma unroll
            for (int i = 0; i < 4; i++)
                #pragma unroll
                for (int j = 0; j < 4; j++) acc[i][j] = fmaf(ar[i], br[j], acc[i][j]);
        }
        __syncthreads();
    }
    #pragma unroll
    for (int i = 0; i < 4; i++) {
        int m = block_m + ty * 4 + i;
        #pragma unroll
        for (int j = 0; j < 4; j++) {
            int n = tx * 4 + j;
            float v = acc[i][j] + fb[n];
            g_h[m * 64 + n] = v > 0.f ? v : 0.f;     // relu
        }
    }
}

// ---------------- K3: FC2 + input-affine + sensory synapse sums ----------------
__global__ void k_sens(const float* __restrict__ fc2w, const float* __restrict__ fc2b,
                       const float* __restrict__ inw,  const float* __restrict__ inb) {
    __shared__ float sh[8][33];
    int warp = threadIdx.x >> 5, lane = threadIdx.x & 31;
    int t = blockIdx.x * 8 + warp;
    float h0 = g_h[t * 64 + lane];
    float h1 = g_h[t * 64 + 32 + lane];
    float y = fc2b[lane];                            // lane = output j (all 32)
    #pragma unroll
    for (int o = 0; o < 32; o++) {
        float hb = __shfl_sync(0xffffffffu, h0, o);
        y = fmaf(fc2w[lane * 64 + o], hb, y);
    }
    #pragma unroll
    for (int o = 0; o < 32; o++) {
        float hb = __shfl_sync(0xffffffffu, h1, o);
        y = fmaf(fc2w[lane * 64 + 32 + o], hb, y);
    }
    float seq = fmaf(y, inw[lane], inb[lane]);
    sh[warp][lane] = seq;
    __syncwarp();
    if (lane < NSZ) {
        float wn = 0.f, wd = 0.f;
        #pragma unroll
        for (int s = 0; s < SSZ; s++) {
            float arg = fmaf(g_sP[s * NSZ + lane], sh[warp][s], g_sQ[s * NSZ + lane]);
            float r = fast_rcp(1.0f + fast_ex2(arg));   // sigmoid
            wn = fmaf(g_sA[s * NSZ + lane], r, wn);
            wd = fmaf(g_sW[s * NSZ + lane], r, wd);
        }
        g_sens[t * 64 + lane]      = wn + g_gvl[lane];  // fold g*vleak into numerator base
        g_sens[t * 64 + 32 + lane] = wd;
    }
}

// ---------------- K4: serial LTC scan (single warp; lane = target neuron) ----------------
__global__ void __launch_bounds__(32, 1)
k_scan(float* __restrict__ out, const float* __restrict__ ow,
       const float* __restrict__ ob) {
    int lane = threadIdx.x;
    bool act = lane < NSZ;
    float P[NSZ], Q[NSZ], A[NSZ], W[NSZ];
    #pragma unroll
    for (int s = 0; s < NSZ; s++) {
        P[s] = act ? g_rP[s * 32 + lane] : 0.f;
        Q[s] = act ? g_rQ[s * 32 + lane] : 0.f;
        A[s] = act ? g_rA[s * 32 + lane] : 0.f;
        W[s] = act ? g_rW[s * 32 + lane] : 0.f;
    }
    float cmt = act ? g_cmt[lane] : 0.f;
    float cg2 = act ? g_cg2[lane] : 1.f;
    float hA  = act ? g_hA[lane]  : 0.f;
    float ow0 = ow[0], ob0 = ob[0];
    float v = 0.f;
    float wnb = act ? g_sens[lane]      : 0.f;
    float wdb = act ? g_sens[32 + lane] : 0.f;
    for (int t = 0; t < BATCH; t++) {
        // prefetch next step's sensory sums (hidden behind the unfold chain)
        float wn_nx = 0.f, wd_nx = 0.f;
        if (act && t + 1 < BATCH) {
            wn_nx = g_sens[(t + 1) * 64 + lane];
            wd_nx = g_sens[(t + 1) * 64 + 32 + lane];
        }
        float wn_base = wnb + hA;    // sensory num + g*vleak + 0.5*sum(wp*erev)
        #pragma unroll
        for (int u = 0; u < UNFOLDS; u++) {
            // 1) broadcast full state first: shfls issue back-to-back
            float vv[NSZ];
            #pragma unroll
            for (int s = 0; s < NSZ; s++) vv[s] = __shfl_sync(0xffffffffu, v, s);
            // 2) independent gate chains, 4-way split accumulators
            float wn0 = wn_base, wn1 = 0.f, wn2 = 0.f, wn3 = 0.f;
            float wd0 = wdb,     wd1 = 0.f, wd2 = 0.f, wd3 = 0.f;
            #pragma unroll
            for (int s = 0; s < NSZ; s++) {
                float arg = fmaf(P[s], vv[s], Q[s]);
                float th  = fast_tanh(arg);          // sigmoid = 0.5 + 0.5*tanh(arg)
                switch (s & 3) {
                    case 0: wn0 = fmaf(A[s], th, wn0); wd0 = fmaf(W[s], th, wd0); break;
                    case 1: wn1 = fmaf(A[s], th, wn1); wd1 = fmaf(W[s], th, wd1); break;
                    case 2: wn2 = fmaf(A[s], th, wn2); wd2 = fmaf(W[s], th, wd2); break;
                    default: wn3 = fmaf(A[s], th, wn3); wd3 = fmaf(W[s], th, wd3); break;
                }
            }
            float wn = (wn0 + wn1) + (wn2 + wn3);
            float wd = (wd0 + wd1) + (wd2 + wd3);
            v = fmaf(cmt, v, wn) * fast_rcp(cg2 + wd);
        }
        if (lane == 0) out[t] = fmaf(v, ow0, ob0);
        wnb = wn_nx; wdb = wd_nx;
    }
}

// ---------------- launch ----------------
extern "C" void kernel_launch(void* const* d_in, const int* in_sizes, int n_in,
                              void* d_out, int out_size) {
    const float* x        = (const float*)d_in[0];
    const float* conv_w   = (const float*)d_in[1];
    const float* conv_b   = (const float*)d_in[2];
    const float* fc1_w    = (const float*)d_in[3];
    const float* fc1_b    = (const float*)d_in[4];
    const float* fc2_w    = (const float*)d_in[5];
    const float* fc2_b    = (const float*)d_in[6];
    const float* input_w  = (const float*)d_in[7];
    const float* input_b  = (const float*)d_in[8];
    const float* s_w      = (const float*)d_in[9];
    const float* s_mu     = (const float*)d_in[10];
    const float* s_sigma  = (const float*)d_in[11];
    const float* s_erev   = (const float*)d_in[12];
    const float* s_mask   = (const float*)d_in[13];
    const float* w        = (const float*)d_in[14];
    const float* mu       = (const float*)d_in[15];
    const float* sigma    = (const float*)d_in[16];
    const float* erev     = (const float*)d_in[17];
    const float* mask     = (const float*)d_in[18];
    const float* gleak    = (const float*)d_in[19];
    const float* vleak    = (const float*)d_in[20];
    const float* cm       = (const float*)d_in[21];
    const float* output_w = (const float*)d_in[22];
    const float* output_b = (const float*)d_in[23];

    k_prep<<<1, 640>>>(w, mu, sigma, erev, mask, gleak, vleak, cm,
                       s_w, s_mu, s_sigma, s_erev, s_mask);
    k_conv<<<BATCH, 256>>>(x, conv_w, conv_b);
    k_fc1<<<BATCH / 64, 256>>>(fc1_w, fc1_b);
    k_sens<<<BATCH / 8, 256>>>(fc2_w, fc2_b, input_w, input_b);
    k_scan<<<1, 32>>>((float*)d_out, output_w, output_b);
}

// round 3
// speedup vs baseline: 6.2242x; 1.7302x over previous
#include <cuda_runtime.h>
#include <math.h>

#define BATCH 8192
#define CONV_OUT 5104      // 8 * 22 * 29
#define SSZ 32
#define NSZ 19
#define UNFOLDS 6
#define L2E 1.4426950408889634f

// ---------------- static scratch (no allocations allowed) ----------------
__device__ float g_act[(size_t)BATCH * CONV_OUT];   // conv+ELU output, 167 MB
__device__ float g_h[BATCH * 64];                   // FC1+relu output
__device__ float g_sens[BATCH * 64];                // [t][0..18]=wnum_s+g*vleak, [t][32..50]=wden_s
// transformed recurrent params for tanh form, [src][32] stride-32 padded
__device__ float g_rP[NSZ * 32], g_rQ[NSZ * 32], g_rA[NSZ * 32], g_rW[NSZ * 32];
__device__ float g_cmt[32], g_cg2[32], g_gvl[32], g_hA[32];
// transformed sensory params (sigmoid ex2 form), [s][n] stride NSZ
__device__ float g_sP[SSZ * NSZ], g_sQ[SSZ * NSZ], g_sA[SSZ * NSZ], g_sW[SSZ * NSZ];

__device__ __forceinline__ float fast_ex2(float x) {
    float y; asm("ex2.approx.f32 %0, %1;" : "=f"(y) : "f"(x)); return y;
}
__device__ __forceinline__ float fast_rcp(float x) {
    float y; asm("rcp.approx.f32 %0, %1;" : "=f"(y) : "f"(x)); return y;
}
__device__ __forceinline__ float fast_tanh(float x) {
    float y; asm("tanh.approx.f32 %0, %1;" : "=f"(y) : "f"(x)); return y;
}

// ---------------- K0: parameter transforms (runs once per launch) ----------------
__global__ void k_prep(const float* __restrict__ w,     const float* __restrict__ mu,
                       const float* __restrict__ sigma, const float* __restrict__ erev,
                       const float* __restrict__ mask,
                       const float* __restrict__ gleak, const float* __restrict__ vleak,
                       const float* __restrict__ cm,
                       const float* __restrict__ sw,    const float* __restrict__ smu,
                       const float* __restrict__ ssig,  const float* __restrict__ serev,
                       const float* __restrict__ smask) {
    int i = threadIdx.x;
    if (i < NSZ * NSZ) {
        int s = i / NSZ, n = i % NSZ;
        float wp = log1pf(expf(w[i])) * mask[i];     // softplus(w) * mask
        // sigmoid(sigma*(v-mu)) = 0.5 + 0.5*tanh(0.5*sigma*(v-mu))
        g_rP[s * 32 + n] =  0.5f * sigma[i];
        g_rQ[s * 32 + n] = -0.5f * sigma[i] * mu[i];
        g_rA[s * 32 + n] =  0.5f * wp * erev[i];     // coefficient of tanh in numerator
        g_rW[s * 32 + n] =  0.5f * wp;               // coefficient of tanh in denominator
    }
    if (i < SSZ * NSZ) {
        float sp = log1pf(expf(sw[i])) * smask[i];
        g_sP[i] = -ssig[i] * L2E;
        g_sQ[i] =  ssig[i] * smu[i] * L2E;
        g_sA[i] =  sp * serev[i];
        g_sW[i] =  sp;
    }
    __syncthreads();
    if (i < NSZ) {
        float g   = log1pf(expf(gleak[i]));
        float cmt = log1pf(expf(cm[i])) * (float)UNFOLDS;
        float sumA = 0.f, sumW = 0.f;
        for (int s = 0; s < NSZ; s++) { sumA += g_rA[s * 32 + i]; sumW += g_rW[s * 32 + i]; }
        g_cmt[i] = cmt;
        g_cg2[i] = cmt + g + 1e-8f + sumW;           // denom const (+EPS +0.5*sum wp)
        g_gvl[i] = g * vleak[i];                     // numerator constant part
        g_hA[i]  = sumA;                             // numerator constant: 0.5*sum(wp*erev)
    }
}

// ---------------- K1: conv 2x2 VALID + ELU, flattened NCHW ----------------
__global__ void k_conv(const float* __restrict__ x, const float* __restrict__ cw,
                       const float* __restrict__ cb) {
    __shared__ float sx[3 * 23 * 30];   // 2070
    __shared__ float swt[96];
    __shared__ float sb[8];
    int b = blockIdx.x;
    const float* xb = x + (size_t)b * 2070;
    for (int i = threadIdx.x; i < 2070; i += blockDim.x) sx[i] = xb[i];
    if (threadIdx.x < 96) swt[threadIdx.x] = cw[threadIdx.x];
    if (threadIdx.x < 8)  sb[threadIdx.x] = cb[threadIdx.x];
    __syncthreads();
    float* ob = g_act + (size_t)b * CONV_OUT;
    for (int o = threadIdx.x; o < CONV_OUT; o += blockDim.x) {
        int c = o / 638;          // 22*29
        int r = o % 638;
        int i = r / 29, j = r % 29;
        float acc = sb[c];
        #pragma unroll
        for (int ci = 0; ci < 3; ci++)
            #pragma unroll
            for (int ki = 0; ki < 2; ki++)
                #pragma unroll
                for (int kj = 0; kj < 2; kj++)
                    acc = fmaf(sx[ci * 690 + (i + ki) * 30 + (j + kj)],
                               swt[c * 12 + ci * 4 + ki * 2 + kj], acc);
        ob[o] = acc > 0.f ? acc : expm1f(acc);       // ELU
    }
}

// ---------------- K2: FC1 GEMM (8192x64, K=5104) + bias + relu ----------------
__global__ void k_fc1(const float* __restrict__ fw, const float* __restrict__ fb) {
    __shared__ float As[16][68];
    __shared__ float Bs[16][68];
    int tid = threadIdx.x;
    int block_m = blockIdx.x * 64;
    int tx = tid & 15;         // output-col group
    int ty = tid >> 4;         // batch-row group
    int lm = tid >> 2;         // 0..63 load row
    int lk = (tid & 3) << 2;   // 0,4,8,12
    const float* aptr = g_act + (size_t)(block_m + lm) * CONV_OUT + lk;
    const float* bptr = fw + (size_t)lm * CONV_OUT + lk;
    float acc[4][4];
    #pragma unroll
    for (int i = 0; i < 4; i++)
        #pragma unroll
        for (int j = 0; j < 4; j++) acc[i][j] = 0.f;
    for (int k0 = 0; k0 < CONV_OUT; k0 += 16) {
        float4 a = *(const float4*)(aptr + k0);
        float4 b = *(const float4*)(bptr + k0);
        As[lk + 0][lm] = a.x; As[lk + 1][lm] = a.y; As[lk + 2][lm] = a.z; As[lk + 3][lm] = a.w;
        Bs[lk + 0][lm] = b.x; Bs[lk + 1][lm] = b.y; Bs[lk + 2][lm] = b.z; Bs[lk + 3][lm] = b.w;
        __syncthreads();
        #pragma unroll
        for (int k = 0; k < 16; k++) {
            float ar[4], br[4];
            #pragma unroll
            for (int i = 0; i < 4; i++) ar[i] = As[k][ty * 4 + i];
            #pragma unroll
            for (int j = 0; j < 4; j++) br[j] = Bs[k][tx * 4 + j];
            #pragma unroll
            for (int i = 0; i < 4; i++)
                #pragma unroll
                for (int j = 0; j < 4; j++) acc[i][j] = fmaf(ar[i], br[j], acc[i][j]);
        }
        __syncthreads();
    }
    #pragma unroll
    for (int i = 0; i < 4; i++) {
        int m = block_m + ty * 4 + i;
        #pragma unroll
        for (int j = 0; j < 4; j++) {
            int n = tx * 4 + j;
            float v = acc[i][j] + fb[n];
            g_h[m * 64 + n] = v > 0.f ? v : 0.f;     // relu
        }
    }
}

// ---------------- K3: FC2 + input-affine + sensory synapse sums ----------------
__global__ void k_sens(const float* __restrict__ fc2w, const float* __restrict__ fc2b,
                       const float* __restrict__ inw,  const float* __restrict__ inb) {
    __shared__ float sh[8][33];
    int warp = threadIdx.x >> 5, lane = threadIdx.x & 31;
    int t = blockIdx.x * 8 + warp;
    float h0 = g_h[t * 64 + lane];
    float h1 = g_h[t * 64 + 32 + lane];
    float y = fc2b[lane];                            // lane = output j (all 32)
    #pragma unroll
    for (int o = 0; o < 32; o++) {
        float hb = __shfl_sync(0xffffffffu, h0, o);
        y = fmaf(fc2w[lane * 64 + o], hb, y);
    }
    #pragma unroll
    for (int o = 0; o < 32; o++) {
        float hb = __shfl_sync(0xffffffffu, h1, o);
        y = fmaf(fc2w[lane * 64 + 32 + o], hb, y);
    }
    float seq = fmaf(y, inw[lane], inb[lane]);
    sh[warp][lane] = seq;
    __syncwarp();
    if (lane < NSZ) {
        float wn = 0.f, wd = 0.f;
        #pragma unroll
        for (int s = 0; s < SSZ; s++) {
            float arg = fmaf(g_sP[s * NSZ + lane], sh[warp][s], g_sQ[s * NSZ + lane]);
            float r = fast_rcp(1.0f + fast_ex2(arg));   // sigmoid
            wn = fmaf(g_sA[s * NSZ + lane], r, wn);
            wd = fmaf(g_sW[s * NSZ + lane], r, wd);
        }
        g_sens[t * 64 + lane]      = wn + g_gvl[lane];  // fold g*vleak into numerator base
        g_sens[t * 64 + 32 + lane] = wd;
    }
}

// ---------------- K4: serial LTC scan (4 warps = 4 SMSPs; sources split across warps,
//                      lane = target neuron, v replicated per warp) ----------------
#define SRC_PER_WARP 5
__global__ void __launch_bounds__(128, 1)
k_scan(float* __restrict__ out, const float* __restrict__ ow,
       const float* __restrict__ ob) {
    __shared__ float s_wn[2][4][32];
    __shared__ float s_wd[2][4][32];
    int tid = threadIdx.x, w = tid >> 5, lane = tid & 31;
    bool act = lane < NSZ;
    // this warp's source slice (zero-padded: source 19 contributes exactly 0)
    float P[SRC_PER_WARP], Q[SRC_PER_WARP], A[SRC_PER_WARP], W[SRC_PER_WARP];
    int srcl[SRC_PER_WARP];
    #pragma unroll
    for (int c = 0; c < SRC_PER_WARP; c++) {
        int s = w * SRC_PER_WARP + c;
        bool ok = act && (s < NSZ);
        srcl[c] = s < NSZ ? s : 0;                 // shfl source lane (dummy -> lane 0)
        P[c] = ok ? g_rP[s * 32 + lane] : 0.f;
        Q[c] = ok ? g_rQ[s * 32 + lane] : 0.f;
        A[c] = ok ? g_rA[s * 32 + lane] : 0.f;
        W[c] = ok ? g_rW[s * 32 + lane] : 0.f;
    }
    float cmt = act ? g_cmt[lane] : 0.f;
    float cg2 = act ? g_cg2[lane] : 1.f;
    float hA  = act ? g_hA[lane]  : 0.f;
    float ow0 = ow[0], ob0 = ob[0];
    float v = 0.f;
    float wnb = act ? g_sens[lane]      : 0.f;
    float wdb = act ? g_sens[32 + lane] : 0.f;
    int buf = 0;
    for (int t = 0; t < BATCH; t++) {
        // prefetch next step's sensory sums (hidden behind the unfold chain)
        float wn_nx = 0.f, wd_nx = 0.f;
        if (act && t + 1 < BATCH) {
            wn_nx = g_sens[(t + 1) * 64 + lane];
            wd_nx = g_sens[(t + 1) * 64 + 32 + lane];
        }
        float wn_base = wnb + hA;    // sensory num + g*vleak + 0.5*sum(wp*erev)
        #pragma unroll
        for (int u = 0; u < UNFOLDS; u++) {
            // 1) broadcast this warp's source states (v replicated in every warp)
            float vv[SRC_PER_WARP];
            #pragma unroll
            for (int c = 0; c < SRC_PER_WARP; c++)
                vv[c] = __shfl_sync(0xffffffffu, v, srcl[c]);
            // 2) gates + 2-way split partial accumulation (5 sources)
            float pn0 = 0.f, pn1 = 0.f, pd0 = 0.f, pd1 = 0.f;
            #pragma unroll
            for (int c = 0; c < SRC_PER_WARP; c++) {
                float arg = fmaf(P[c], vv[c], Q[c]);
                float th  = fast_tanh(arg);          // sigmoid = 0.5 + 0.5*tanh
                if (c & 1) { pn1 = fmaf(A[c], th, pn1); pd1 = fmaf(W[c], th, pd1); }
                else       { pn0 = fmaf(A[c], th, pn0); pd0 = fmaf(W[c], th, pd0); }
            }
            float own_n = pn0 + pn1, own_d = pd0 + pd1;
            s_wn[buf][w][lane] = own_n;
            s_wd[buf][w][lane] = own_d;
            __syncthreads();                          // one barrier per unfold
            // 3) replicated reduction + state update (own partial stays in regs)
            float wn = wn_base + own_n;
            float wd = wdb + own_d;
            #pragma unroll
            for (int j = 0; j < 4; j++) {
                if (j == w) continue;
                wn += s_wn[buf][j][lane];
                wd += s_wd[buf][j][lane];
            }
            v = fmaf(cmt, v, wn) * fast_rcp(cg2 + wd);
            buf ^= 1;                                 // double buffer: no 2nd barrier
        }
        if (tid == 0) out[t] = fmaf(v, ow0, ob0);
        wnb = wn_nx; wdb = wd_nx;
    }
}

// ---------------- launch ----------------
extern "C" void kernel_launch(void* const* d_in, const int* in_sizes, int n_in,
                              void* d_out, int out_size) {
    const float* x        = (const float*)d_in[0];
    const float* conv_w   = (const float*)d_in[1];
    const float* conv_b   = (const float*)d_in[2];
    const float* fc1_w    = (const float*)d_in[3];
    const float* fc1_b    = (const float*)d_in[4];
    const float* fc2_w    = (const float*)d_in[5];
    const float* fc2_b    = (const float*)d_in[6];
    const float* input_w  = (const float*)d_in[7];
    const float* input_b  = (const float*)d_in[8];
    const float* s_w      = (const float*)d_in[9];
    const float* s_mu     = (const float*)d_in[10];
    const float* s_sigma  = (const float*)d_in[11];
    const float* s_erev   = (const float*)d_in[12];
    const float* s_mask   = (const float*)d_in[13];
    const float* w        = (const float*)d_in[14];
    const float* mu       = (const float*)d_in[15];
    const float* sigma    = (const float*)d_in[16];
    const float* erev     = (const float*)d_in[17];
    const float* mask     = (const float*)d_in[18];
    const float* gleak    = (const float*)d_in[19];
    const float* vleak    = (const float*)d_in[20];
    const float* cm       = (const float*)d_in[21];
    const float* output_w = (const float*)d_in[22];
    const float* output_b = (const float*)d_in[23];

    k_prep<<<1, 640>>>(w, mu, sigma, erev, mask, gleak, vleak, cm,
                       s_w, s_mu, s_sigma, s_erev, s_mask);
    k_conv<<<BATCH, 256>>>(x, conv_w, conv_b);
    k_fc1<<<BATCH / 64, 256>>>(fc1_w, fc1_b);
    k_sens<<<BATCH / 8, 256>>>(fc2_w, fc2_b, input_w, input_b);
    k_scan<<<1, 128>>>((float*)d_out, output_w, output_b);
}

// round 4
// speedup vs baseline: 7.2167x; 1.1595x over previous
#include <cuda_runtime.h>
#include <math.h>

#define BATCH 8192
#define CONV_OUT 5104      // 8 * 22 * 29
#define SSZ 32
#define NSZ 19
#define UNFOLDS 6
#define L2E 1.4426950408889634f

// ---------------- static scratch (no allocations allowed) ----------------
__device__ float g_act[(size_t)BATCH * CONV_OUT];   // conv+ELU output, 167 MB
__device__ float g_h[BATCH * 64];                   // FC1+relu output
__device__ float2 g_sens2[BATCH * 32];              // [t][lane] = (wnum_s + g*vleak, wden_s)
// transformed recurrent params for tanh form, [src][32] stride-32 padded
__device__ float g_rP[NSZ * 32], g_rQ[NSZ * 32], g_rA[NSZ * 32], g_rW[NSZ * 32];
__device__ float g_cmt[32], g_cg2[32], g_gvl[32], g_hA[32];
// transformed sensory params (sigmoid ex2 form), [s][n] stride NSZ
__device__ float g_sP[SSZ * NSZ], g_sQ[SSZ * NSZ], g_sA[SSZ * NSZ], g_sW[SSZ * NSZ];

__device__ __forceinline__ float fast_ex2(float x) {
    float y; asm("ex2.approx.f32 %0, %1;" : "=f"(y) : "f"(x)); return y;
}
__device__ __forceinline__ float fast_rcp(float x) {
    float y; asm("rcp.approx.f32 %0, %1;" : "=f"(y) : "f"(x)); return y;
}
__device__ __forceinline__ float fast_tanh(float x) {
    float y; asm("tanh.approx.f32 %0, %1;" : "=f"(y) : "f"(x)); return y;
}

// ---------------- K0: parameter transforms (runs once per launch) ----------------
__global__ void k_prep(const float* __restrict__ w,     const float* __restrict__ mu,
                       const float* __restrict__ sigma, const float* __restrict__ erev,
                       const float* __restrict__ mask,
                       const float* __restrict__ gleak, const float* __restrict__ vleak,
                       const float* __restrict__ cm,
                       const float* __restrict__ sw,    const float* __restrict__ smu,
                       const float* __restrict__ ssig,  const float* __restrict__ serev,
                       const float* __restrict__ smask) {
    int i = threadIdx.x;
    if (i < NSZ * NSZ) {
        int s = i / NSZ, n = i % NSZ;
        float wp = log1pf(expf(w[i])) * mask[i];     // softplus(w) * mask
        // sigmoid(sigma*(v-mu)) = 0.5 + 0.5*tanh(0.5*sigma*(v-mu))
        g_rP[s * 32 + n] =  0.5f * sigma[i];
        g_rQ[s * 32 + n] = -0.5f * sigma[i] * mu[i];
        g_rA[s * 32 + n] =  0.5f * wp * erev[i];     // coefficient of tanh in numerator
        g_rW[s * 32 + n] =  0.5f * wp;               // coefficient of tanh in denominator
    }
    if (i < SSZ * NSZ) {
        float sp = log1pf(expf(sw[i])) * smask[i];
        g_sP[i] = -ssig[i] * L2E;
        g_sQ[i] =  ssig[i] * smu[i] * L2E;
        g_sA[i] =  sp * serev[i];
        g_sW[i] =  sp;
    }
    __syncthreads();
    if (i < NSZ) {
        float g   = log1pf(expf(gleak[i]));
        float cmt = log1pf(expf(cm[i])) * (float)UNFOLDS;
        float sumA = 0.f, sumW = 0.f;
        for (int s = 0; s < NSZ; s++) { sumA += g_rA[s * 32 + i]; sumW += g_rW[s * 32 + i]; }
        g_cmt[i] = cmt;
        g_cg2[i] = cmt + g + 1e-8f + sumW;           // denom const (+EPS +0.5*sum wp)
        g_gvl[i] = g * vleak[i];                     // numerator constant part
        g_hA[i]  = sumA;                             // numerator constant: 0.5*sum(wp*erev)
    }
}

// ---------------- K1: conv 2x2 VALID + ELU, flattened NCHW ----------------
__global__ void k_conv(const float* __restrict__ x, const float* __restrict__ cw,
                       const float* __restrict__ cb) {
    __shared__ float sx[3 * 23 * 30];   // 2070
    __shared__ float swt[96];
    __shared__ float sb[8];
    int b = blockIdx.x;
    const float* xb = x + (size_t)b * 2070;
    for (int i = threadIdx.x; i < 2070; i += blockDim.x) sx[i] = xb[i];
    if (threadIdx.x < 96) swt[threadIdx.x] = cw[threadIdx.x];
    if (threadIdx.x < 8)  sb[threadIdx.x] = cb[threadIdx.x];
    __syncthreads();
    float* ob = g_act + (size_t)b * CONV_OUT;
    for (int o = threadIdx.x; o < CONV_OUT; o += blockDim.x) {
        int c = o / 638;          // 22*29
        int r = o % 638;
        int i = r / 29, j = r % 29;
        float acc = sb[c];
        #pragma unroll
        for (int ci = 0; ci < 3; ci++)
            #pragma unroll
            for (int ki = 0; ki < 2; ki++)
                #pragma unroll
                for (int kj = 0; kj < 2; kj++)
                    acc = fmaf(sx[ci * 690 + (i + ki) * 30 + (j + kj)],
                               swt[c * 12 + ci * 4 + ki * 2 + kj], acc);
        ob[o] = acc > 0.f ? acc : expm1f(acc);       // ELU
    }
}

// ---------------- K2: FC1 GEMM (8192x64, K=5104) + bias + relu ----------------
__global__ void k_fc1(const float* __restrict__ fw, const float* __restrict__ fb) {
    __shared__ float As[16][68];
    __shared__ float Bs[16][68];
    int tid = threadIdx.x;
    int block_m = blockIdx.x * 64;
    int tx = tid & 15;         // output-col group
    int ty = tid >> 4;         // batch-row group
    int lm = tid >> 2;         // 0..63 load row
    int lk = (tid & 3) << 2;   // 0,4,8,12
    const float* aptr = g_act + (size_t)(block_m + lm) * CONV_OUT + lk;
    const float* bptr = fw + (size_t)lm * CONV_OUT + lk;
    float acc[4][4];
    #pragma unroll
    for (int i = 0; i < 4; i++)
        #pragma unroll
        for (int j = 0; j < 4; j++) acc[i][j] = 0.f;
    for (int k0 = 0; k0 < CONV_OUT; k0 += 16) {
        float4 a = *(const float4*)(aptr + k0);
        float4 b = *(const float4*)(bptr + k0);
        As[lk + 0][lm] = a.x; As[lk + 1][lm] = a.y; As[lk + 2][lm] = a.z; As[lk + 3][lm] = a.w;
        Bs[lk + 0][lm] = b.x; Bs[lk + 1][lm] = b.y; Bs[lk + 2][lm] = b.z; Bs[lk + 3][lm] = b.w;
        __syncthreads();
        #pragma unroll
        for (int k = 0; k < 16; k++) {
            float ar[4], br[4];
            #pragma unroll
            for (int i = 0; i < 4; i++) ar[i] = As[k][ty * 4 + i];
            #pragma unroll
            for (int j = 0; j < 4; j++) br[j] = Bs[k][tx * 4 + j];
            #pragma unroll
            for (int i = 0; i < 4; i++)
                #pragma unroll
                for (int j = 0; j < 4; j++) acc[i][j] = fmaf(ar[i], br[j], acc[i][j]);
        }
        __syncthreads();
    }
    #pragma unroll
    for (int i = 0; i < 4; i++) {
        int m = block_m + ty * 4 + i;
        #pragma unroll
        for (int j = 0; j < 4; j++) {
            int n = tx * 4 + j;
            float v = acc[i][j] + fb[n];
            g_h[m * 64 + n] = v > 0.f ? v : 0.f;     // relu
        }
    }
}

// ---------------- K3: FC2 + input-affine + sensory synapse sums ----------------
__global__ void k_sens(const float* __restrict__ fc2w, const float* __restrict__ fc2b,
                       const float* __restrict__ inw,  const float* __restrict__ inb) {
    __shared__ float sh[8][33];
    int warp = threadIdx.x >> 5, lane = threadIdx.x & 31;
    int t = blockIdx.x * 8 + warp;
    float h0 = g_h[t * 64 + lane];
    float h1 = g_h[t * 64 + 32 + lane];
    float y = fc2b[lane];                            // lane = output j (all 32)
    #pragma unroll
    for (int o = 0; o < 32; o++) {
        float hb = __shfl_sync(0xffffffffu, h0, o);
        y = fmaf(fc2w[lane * 64 + o], hb, y);
    }
    #pragma unroll
    for (int o = 0; o < 32; o++) {
        float hb = __shfl_sync(0xffffffffu, h1, o);
        y = fmaf(fc2w[lane * 64 + 32 + o], hb, y);
    }
    float seq = fmaf(y, inw[lane], inb[lane]);
    sh[warp][lane] = seq;
    __syncwarp();
    if (lane < NSZ) {
        float wn = 0.f, wd = 0.f;
        #pragma unroll
        for (int s = 0; s < SSZ; s++) {
            float arg = fmaf(g_sP[s * NSZ + lane], sh[warp][s], g_sQ[s * NSZ + lane]);
            float r = fast_rcp(1.0f + fast_ex2(arg));   // sigmoid
            wn = fmaf(g_sA[s * NSZ + lane], r, wn);
            wd = fmaf(g_sW[s * NSZ + lane], r, wd);
        }
        g_sens2[t * 32 + lane] = make_float2(wn + g_gvl[lane], wd);
    }
}

// ---------------- K4: serial LTC scan (4 warps = 4 SMSPs; sources split across warps,
//                      lane = target neuron, v replicated per warp) ----------------
__global__ void __launch_bounds__(128, 1)
k_scan(float* __restrict__ out, const float* __restrict__ ow,
       const float* __restrict__ ob) {
    __shared__ float2 s_p[2][4][32];                  // packed (wn, wd) partials
    int tid = threadIdx.x, w = tid >> 5, lane = tid & 31;
    bool act = lane < NSZ;
    // this warp's source slice (zero-padded: source 19 contributes exactly 0)
    float P[5], Q[5], A[5], W[5];
    int srcl[5];
    #pragma unroll
    for (int c = 0; c < 5; c++) {
        int s = w * 5 + c;
        bool ok = act && (s < NSZ);
        srcl[c] = s < NSZ ? s : 0;                 // shfl source lane (dummy -> lane 0)
        P[c] = ok ? g_rP[s * 32 + lane] : 0.f;
        Q[c] = ok ? g_rQ[s * 32 + lane] : 0.f;
        A[c] = ok ? g_rA[s * 32 + lane] : 0.f;
        W[c] = ok ? g_rW[s * 32 + lane] : 0.f;
    }
    float cmt = act ? g_cmt[lane] : 0.f;
    float cg2 = act ? g_cg2[lane] : 1.f;
    float hA  = act ? g_hA[lane]  : 0.f;
    float ow0 = ow[0], ob0 = ob[0];
    float v = 0.f;
    float2 sb = g_sens2[lane];                        // step 0 sensory (zeros for lane>=19)
    #pragma unroll 2
    for (int t = 0; t < BATCH; t++) {
        // unguarded prefetch (wraps to row 0 on last step; value unused)
        float2 nx = g_sens2[((t + 1) & (BATCH - 1)) * 32 + lane];
        float wn_base = sb.x + hA;    // sensory num + g*vleak + 0.5*sum(wp*erev)
        float wdb = sb.y;
        #pragma unroll
        for (int u = 0; u < UNFOLDS; u++) {
            // 1) broadcast this warp's source states (v replicated in every warp)
            float vv0 = __shfl_sync(0xffffffffu, v, srcl[0]);
            float vv1 = __shfl_sync(0xffffffffu, v, srcl[1]);
            float vv2 = __shfl_sync(0xffffffffu, v, srcl[2]);
            float vv3 = __shfl_sync(0xffffffffu, v, srcl[3]);
            float vv4 = __shfl_sync(0xffffffffu, v, srcl[4]);
            // 2) gates (independent tanh chains)
            float t0 = fast_tanh(fmaf(P[0], vv0, Q[0]));
            float t1 = fast_tanh(fmaf(P[1], vv1, Q[1]));
            float t2 = fast_tanh(fmaf(P[2], vv2, Q[2]));
            float t3 = fast_tanh(fmaf(P[3], vv3, Q[3]));
            float t4 = fast_tanh(fmaf(P[4], vv4, Q[4]));
            // trees end on the latest tanh (t4)
            float pn = fmaf(A[4], t4, fmaf(A[0], t0, A[2] * t2) + fmaf(A[1], t1, A[3] * t3));
            float pd = fmaf(W[4], t4, fmaf(W[0], t0, W[2] * t2) + fmaf(W[1], t1, W[3] * t3));
            s_p[u & 1][w][lane] = make_float2(pn, pd);
            __syncthreads();                          // one barrier per unfold
            // 3) read ALL four partials (own included; no runtime branch), tree-sum
            float2 o0 = s_p[u & 1][0][lane];
            float2 o1 = s_p[u & 1][1][lane];
            float2 o2 = s_p[u & 1][2][lane];
            float2 o3 = s_p[u & 1][3][lane];
            float wn = (wn_base + o0.x) + (o1.x + o2.x) + o3.x;
            float wd = (wdb + o0.y) + (o1.y + o2.y) + o3.y;
            v = fmaf(cmt, v, wn) * fast_rcp(cg2 + wd);
        }
        if (tid == 0) out[t] = fmaf(v, ow0, ob0);
        sb = nx;
    }
}

// ---------------- launch ----------------
extern "C" void kernel_launch(void* const* d_in, const int* in_sizes, int n_in,
                              void* d_out, int out_size) {
    const float* x        = (const float*)d_in[0];
    const float* conv_w   = (const float*)d_in[1];
    const float* conv_b   = (const float*)d_in[2];
    const float* fc1_w    = (const float*)d_in[3];
    const float* fc1_b    = (const float*)d_in[4];
    const float* fc2_w    = (const float*)d_in[5];
    const float* fc2_b    = (const float*)d_in[6];
    const float* input_w  = (const float*)d_in[7];
    const float* input_b  = (const float*)d_in[8];
    const float* s_w      = (const float*)d_in[9];
    const float* s_mu     = (const float*)d_in[10];
    const float* s_sigma  = (const float*)d_in[11];
    const float* s_erev   = (const float*)d_in[12];
    const float* s_mask   = (const float*)d_in[13];
    const float* w        = (const float*)d_in[14];
    const float* mu       = (const float*)d_in[15];
    const float* sigma    = (const float*)d_in[16];
    const float* erev     = (const float*)d_in[17];
    const float* mask     = (const float*)d_in[18];
    const float* gleak    = (const float*)d_in[19];
    const float* vleak    = (const float*)d_in[20];
    const float* cm       = (const float*)d_in[21];
    const float* output_w = (const float*)d_in[22];
    const float* output_b = (const float*)d_in[23];

    k_prep<<<1, 640>>>(w, mu, sigma, erev, mask, gleak, vleak, cm,
                       s_w, s_mu, s_sigma, s_erev, s_mask);
    k_conv<<<BATCH, 256>>>(x, conv_w, conv_b);
    k_fc1<<<BATCH / 64, 256>>>(fc1_w, fc1_b);
    k_sens<<<BATCH / 8, 256>>>(fc2_w, fc2_b, input_w, input_b);
    k_scan<<<1, 128>>>((float*)d_out, output_w, output_b);
}